// round 6
// baseline (speedup 1.0000x reference)
#include <cuda_runtime.h>
#include <math.h>

#define T_STEPS 500
#define BATCH   128
#define FDIM    128
#define HDIM    512
#define ODIM    32

#define NG  16     // batch groups (clusters)
#define GSZ 8      // batches per group
#define NS  8      // H slices = CTAs per cluster
#define DSTW 64    // dst neurons per slice

#define GBM 128
#define GBN 128
#define GBK 32

// Device-global scratch (sanctioned allocation-free path)
__device__ float g_iin[T_STEPS * BATCH * HDIM];          // x @ W_in^T
__device__ float g_wrecT[HDIM * HDIM];                   // W_rec^T [src][dst]
__device__ float g_woutT[HDIM * ODIM];                   // W_out^T [h][o]
__device__ unsigned long long g_zall[T_STEPS * NG * GSZ * NS];  // spike masks

// ---------------------------------------------------------------------------
__device__ __forceinline__ unsigned smem_u32(const void* p) {
    unsigned a;
    asm("{ .reg .u64 t; cvta.to.shared.u64 t, %1; cvt.u32.u64 %0, t; }"
        : "=r"(a) : "l"(p));
    return a;
}
__device__ __forceinline__ void st_cluster_u64(unsigned laddr, int rank,
                                               unsigned long long v) {
    unsigned rem;
    asm volatile("mapa.shared::cluster.u32 %0, %1, %2;"
                 : "=r"(rem) : "r"(laddr), "r"(rank));
    asm volatile("st.shared::cluster.u64 [%0], %1;"
                 :: "r"(rem), "l"(v) : "memory");
}
#define CLUSTER_ARRIVE() asm volatile("barrier.cluster.arrive.aligned;" ::: "memory")
#define CLUSTER_WAIT()   asm volatile("barrier.cluster.wait.aligned;"   ::: "memory")

// ---------------------------------------------------------------------------
// Transposes
// ---------------------------------------------------------------------------
__global__ void transpose_kernel(const float* __restrict__ W_rec,
                                 const float* __restrict__ W_out) {
    int idx = blockIdx.x * blockDim.x + threadIdx.x;
    if (idx < HDIM * HDIM) {
        int r = idx / HDIM, c = idx % HDIM;
        g_wrecT[c * HDIM + r] = W_rec[idx];
    }
    if (idx < ODIM * HDIM) {
        int o = idx / HDIM, h = idx % HDIM;
        g_woutT[h * ODIM + o] = W_out[idx];
    }
}

// ---------------------------------------------------------------------------
// GEMM: g_iin[m,n] = sum_k X[m,k] * W_in[n,k]   (verbatim — verified)
// ---------------------------------------------------------------------------
__global__ void __launch_bounds__(256) gemm_iin_kernel(
    const float* __restrict__ X, const float* __restrict__ Win) {
    __shared__ float As[GBK][GBM + 4];
    __shared__ float Bs[GBK][GBN + 4];

    const int tid = threadIdx.x;
    const int bm = blockIdx.y;
    const int bn = blockIdx.x;
    const float* Xb = X   + (size_t)bm * GBM * FDIM;
    const float* Wb = Win + (size_t)bn * GBN * FDIM;

    const int ty = tid >> 4;
    const int tx = tid & 15;
    const int lrow = tid >> 3;
    const int lcol = (tid & 7) * 4;

    float acc[8][8] = {};

    for (int k0 = 0; k0 < FDIM; k0 += GBK) {
        #pragma unroll
        for (int p = 0; p < 4; p++) {
            int r = lrow + p * 32;
            float4 va = *(const float4*)(Xb + (size_t)r * FDIM + k0 + lcol);
            As[lcol + 0][r] = va.x; As[lcol + 1][r] = va.y;
            As[lcol + 2][r] = va.z; As[lcol + 3][r] = va.w;
            float4 vb = *(const float4*)(Wb + (size_t)r * FDIM + k0 + lcol);
            Bs[lcol + 0][r] = vb.x; Bs[lcol + 1][r] = vb.y;
            Bs[lcol + 2][r] = vb.z; Bs[lcol + 3][r] = vb.w;
        }
        __syncthreads();

        #pragma unroll
        for (int k = 0; k < GBK; k++) {
            float af[8], bf[8];
            *(float4*)(af)     = *(const float4*)&As[k][ty * 8];
            *(float4*)(af + 4) = *(const float4*)&As[k][ty * 8 + 4];
            *(float4*)(bf)     = *(const float4*)&Bs[k][tx * 8];
            *(float4*)(bf + 4) = *(const float4*)&Bs[k][tx * 8 + 4];
            #pragma unroll
            for (int i = 0; i < 8; i++)
                #pragma unroll
                for (int j = 0; j < 8; j++)
                    acc[i][j] += af[i] * bf[j];
        }
        __syncthreads();
    }

    float* C = g_iin + (size_t)(bm * GBM) * HDIM + bn * GBN;
    #pragma unroll
    for (int i = 0; i < 8; i++) {
        float4 v0, v1;
        v0.x = acc[i][0]; v0.y = acc[i][1]; v0.z = acc[i][2]; v0.w = acc[i][3];
        v1.x = acc[i][4]; v1.y = acc[i][5]; v1.z = acc[i][6]; v1.w = acc[i][7];
        float* Crow = C + (size_t)(ty * 8 + i) * HDIM + tx * 8;
        *(float4*)(Crow)     = v0;
        *(float4*)(Crow + 4) = v1;
    }
}

// ---------------------------------------------------------------------------
// SNN kernel: cluster of NS=8 CTAs per batch group. Phase 1: recurrent loop
// with SMEM-cached W slice + DSMEM mask exchange + cluster barrier.
// Phase 2: readout + IIR filter for batch (g*8 + s).
// ---------------------------------------------------------------------------
#define SNN_SMEM 148864

__global__ void __launch_bounds__(512, 1) __cluster_dims__(NS, 1, 1)
snn_kernel(const float* __restrict__ b_out, float* __restrict__ out) {
    extern __shared__ char sh[];
    float*              w_s    = (float*)sh;                         // 131072 B
    int*                s_list = (int*)(sh + 131072);                // 16384 B
    unsigned long long* s_mask = (unsigned long long*)(sh + 147456); // [2][64] 1024 B
    int*                s_cnt  = (int*)(sh + 148480);                // 256 B
    unsigned*           s_half = (unsigned*)(sh + 148736);           // 64 B
    int*                s_n    = (int*)(sh + 148800);                // 32 B

    const int g    = blockIdx.x >> 3;
    const int s    = blockIdx.x & 7;            // == cluster rank
    const int tid  = threadIdx.x;
    const int warp = tid >> 5;
    const int lane = tid & 31;
    const int b    = warp >> 1;                 // local batch 0..7
    const int d    = ((warp & 1) << 5) + lane;  // dst 0..63

    // stage W_recT slice: w_s[h][d] = g_wrecT[h][s*64+d]
    for (int idx = tid; idx < HDIM * DSTW; idx += 512)
        w_s[idx] = g_wrecT[((idx >> 6) << 9) + (s << 6) + (idx & 63)];
    if (tid < 8) s_n[tid] = 0;
    __syncthreads();

    const int gb = (g << 3) + b;
    float v = 0.f, ii = 0.f, aa = 0.f;
    const float* iin = g_iin + (size_t)gb * HDIM + (s << 6) + d;
    const char*  wp  = (const char*)w_s + ((size_t)d << 2);
    const int*   lp  = s_list + (b << 9);

    for (int t = 0; t < T_STEPS; t++) {
        float ic = __ldg(iin + (size_t)t * (BATCH * HDIM));

        // ---- SMEM gather over this batch's offset list ----
        const int nb = s_n[b];
        float a0 = 0.f, a1 = 0.f, a2 = 0.f, a3 = 0.f;
        int j = 0;
        for (; j + 4 <= nb; j += 4) {
            int4 o = *(const int4*)(lp + j);
            a0 += *(const float*)(wp + o.x);
            a1 += *(const float*)(wp + o.y);
            a2 += *(const float*)(wp + o.z);
            a3 += *(const float*)(wp + o.w);
        }
        for (; j < nb; j++)
            a0 += *(const float*)(wp + lp[j]);
        float rec = ((a0 + a1) + (a2 + a3));

        // ---- LIF-AdEx update (grouping mirrors the JAX reference) ----
        float dv   = 0.1f * ((((0.f - v) + 0.5f * expf((v - 1.f) * 2.f)) + ii) - aa);
        float vdec = v + dv;
        float idec = ii - 0.2f * ii;
        float adec = aa + 0.002f * (4.f * v - aa);
        int   z    = (vdec - 1.f) > 0.f;
        v  = z ? 0.f : vdec;
        ii = (idec + ic) + rec;
        aa = adec + (z ? 0.02f : 0.f);

        // ---- pack spike bits ----
        unsigned bal = __ballot_sync(0xffffffffu, z);
        if (lane == 0) s_half[warp] = bal;
        __syncthreads();

        // ---- DSMEM multicast of masks to all cluster peers (double-buffered) ----
        const int p = t & 1;
        if (tid < 64) {
            int r  = tid >> 3;                  // target rank
            int bb = tid & 7;                   // batch
            unsigned long long m64 =
                (unsigned long long)s_half[bb << 1] |
                ((unsigned long long)s_half[(bb << 1) + 1] << 32);
            unsigned laddr = smem_u32(&s_mask[(p << 6) + (bb << 3) + s]);
            st_cluster_u64(laddr, r, m64);
            if (r == s)                         // 8 threads: persist for phase 2
                g_zall[(((size_t)t * NG + g) * GSZ + bb) * NS + s] = m64;
        }
        CLUSTER_ARRIVE();
        CLUSTER_WAIT();                         // all 64 masks now in local s_mask[p]

        // ---- expand masks to per-batch byte-offset lists ----
        if (tid < 64) s_cnt[tid] = __popcll(s_mask[(p << 6) + tid]);
        __syncthreads();
        if (tid < 64) {
            int bb = tid >> 3, w8 = tid & 7;
            int base = 0;
            #pragma unroll
            for (int q = 0; q < 7; q++)
                if (q < w8) base += s_cnt[(bb << 3) + q];
            unsigned long long m = s_mask[(p << 6) + tid];
            int* out_l = s_list + (bb << 9) + base;
            int off0 = w8 << 14;                // (w8*64) rows * 256 B
            while (m) {
                int bit = __ffsll(m) - 1;
                m &= m - 1;
                *out_l++ = off0 + (bit << 8);
            }
            if (w8 == 7) s_n[bb] = base + s_cnt[tid];
        }
        __syncthreads();
    }

    // ================= Phase 2: readout + IIR for batch B = g*8 + s =========
    __threadfence();                            // publish this CTA's g_zall STGs
    CLUSTER_ARRIVE();
    CLUSTER_WAIT();                             // peers' masks visible in L2

    float* y_buf = (float*)sh;                  // reuse w_s region: [500][32]
    const int B = (g << 3) + s;
    float bo = b_out[lane];

    for (int t = warp; t < T_STEPS; t += 16) {
        const unsigned long long* mp =
            g_zall + (((size_t)t * NG + g) * GSZ + s) * NS;
        float y0 = 0.f, y1 = 0.f, y2 = 0.f, y3 = 0.f;
        #pragma unroll
        for (int w8 = 0; w8 < 8; w8++) {
            unsigned long long m = __ldcg(mp + w8);
            const float* wop = g_woutT + (w8 << 11) + lane;
            while (m) {
                int b0 = __ffsll(m) - 1; m &= m - 1;
                int b1 = -1, b2 = -1, b3 = -1;
                if (m) { b1 = __ffsll(m) - 1; m &= m - 1; }
                if (m) { b2 = __ffsll(m) - 1; m &= m - 1; }
                if (m) { b3 = __ffsll(m) - 1; m &= m - 1; }
                y0 += wop[b0 << 5];
                if (b1 >= 0) y1 += wop[b1 << 5];
                if (b2 >= 0) y2 += wop[b2 << 5];
                if (b3 >= 0) y3 += wop[b3 << 5];
            }
        }
        y_buf[t * ODIM + lane] = ((y0 + y1) + (y2 + y3)) + bo;
    }
    __syncthreads();

    if (warp == 0) {
        float o = y_buf[lane];                  // o0 = y[0]
        out[(size_t)B * ODIM + lane] = o;
        for (int t = 1; t < T_STEPS; t++) {
            float y = y_buf[t * ODIM + lane];
            o = o + 0.2231435511314f * (y - o);
            out[((size_t)t * BATCH + B) * ODIM + lane] = o;
        }
    }
}

// ---------------------------------------------------------------------------
extern "C" void kernel_launch(void* const* d_in, const int* in_sizes, int n_in,
                              void* d_out, int out_size) {
    const float* x     = (const float*)d_in[0];  // (T,B,F)
    const float* W_in  = (const float*)d_in[1];  // (H,F)
    const float* W_rec = (const float*)d_in[2];  // (H,H)
    const float* W_out = (const float*)d_in[3];  // (O,H)
    const float* b_out = (const float*)d_in[4];  // (O,)
    float* out = (float*)d_out;                  // (T,B,O)

    cudaFuncSetAttribute(snn_kernel,
                         cudaFuncAttributeMaxDynamicSharedMemorySize, SNN_SMEM);

    transpose_kernel<<<(HDIM * HDIM + 255) / 256, 256>>>(W_rec, W_out);

    dim3 ggrid(HDIM / GBN, (T_STEPS * BATCH) / GBM);  // (4, 500)
    gemm_iin_kernel<<<ggrid, 256>>>(x, W_in);

    snn_kernel<<<NG * NS, 512, SNN_SMEM>>>(b_out, out);
}

// round 7
// speedup vs baseline: 2.3346x; 2.3346x over previous
#include <cuda_runtime.h>
#include <math.h>

#define T_STEPS 500
#define BATCH   128
#define FDIM    128
#define HDIM    512
#define ODIM    32

#define NG  16     // batch groups
#define GSZ 8      // batches per group
#define NS  8      // H slices = CTAs per group
#define DSTW 64    // dst neurons per slice

#define GBM 128
#define GBN 128
#define GBK 32

// Device-global scratch (sanctioned allocation-free path)
__device__ float g_iin[T_STEPS * BATCH * HDIM];          // x @ W_in^T
__device__ float g_wrecT[HDIM * HDIM];                   // W_rec^T [src][dst]
__device__ float g_woutT[HDIM * ODIM];                   // W_out^T [h][o]
__device__ unsigned long long g_zall[T_STEPS * NG * GSZ * NS];  // spike masks
__device__ int   g_flag[T_STEPS * NG * NS];              // per-(t,g,s) publish flag

// ---------------------------------------------------------------------------
__device__ __forceinline__ void st_release_gpu(int* p, int v) {
    asm volatile("st.global.release.gpu.b32 [%0], %1;" :: "l"(p), "r"(v) : "memory");
}
__device__ __forceinline__ int ld_acquire_gpu(const int* p) {
    int v;
    asm volatile("ld.global.acquire.gpu.b32 %0, [%1];" : "=r"(v) : "l"(p) : "memory");
    return v;
}

// ---------------------------------------------------------------------------
// Transposes + zero the per-replay flags
// ---------------------------------------------------------------------------
__global__ void transpose_kernel(const float* __restrict__ W_rec,
                                 const float* __restrict__ W_out) {
    int idx = blockIdx.x * blockDim.x + threadIdx.x;
    if (idx < HDIM * HDIM) {
        int r = idx / HDIM, c = idx % HDIM;
        g_wrecT[c * HDIM + r] = W_rec[idx];
    }
    if (idx < ODIM * HDIM) {
        int o = idx / HDIM, h = idx % HDIM;
        g_woutT[h * ODIM + o] = W_out[idx];
    }
    if (idx < T_STEPS * NG * NS) g_flag[idx] = 0;
}

// ---------------------------------------------------------------------------
// GEMM: g_iin[m,n] = sum_k X[m,k] * W_in[n,k]   (verbatim — verified)
// ---------------------------------------------------------------------------
__global__ void __launch_bounds__(256) gemm_iin_kernel(
    const float* __restrict__ X, const float* __restrict__ Win) {
    __shared__ float As[GBK][GBM + 4];
    __shared__ float Bs[GBK][GBN + 4];

    const int tid = threadIdx.x;
    const int bm = blockIdx.y;
    const int bn = blockIdx.x;
    const float* Xb = X   + (size_t)bm * GBM * FDIM;
    const float* Wb = Win + (size_t)bn * GBN * FDIM;

    const int ty = tid >> 4;
    const int tx = tid & 15;
    const int lrow = tid >> 3;
    const int lcol = (tid & 7) * 4;

    float acc[8][8] = {};

    for (int k0 = 0; k0 < FDIM; k0 += GBK) {
        #pragma unroll
        for (int p = 0; p < 4; p++) {
            int r = lrow + p * 32;
            float4 va = *(const float4*)(Xb + (size_t)r * FDIM + k0 + lcol);
            As[lcol + 0][r] = va.x; As[lcol + 1][r] = va.y;
            As[lcol + 2][r] = va.z; As[lcol + 3][r] = va.w;
            float4 vb = *(const float4*)(Wb + (size_t)r * FDIM + k0 + lcol);
            Bs[lcol + 0][r] = vb.x; Bs[lcol + 1][r] = vb.y;
            Bs[lcol + 2][r] = vb.z; Bs[lcol + 3][r] = vb.w;
        }
        __syncthreads();

        #pragma unroll
        for (int k = 0; k < GBK; k++) {
            float af[8], bf[8];
            *(float4*)(af)     = *(const float4*)&As[k][ty * 8];
            *(float4*)(af + 4) = *(const float4*)&As[k][ty * 8 + 4];
            *(float4*)(bf)     = *(const float4*)&Bs[k][tx * 8];
            *(float4*)(bf + 4) = *(const float4*)&Bs[k][tx * 8 + 4];
            #pragma unroll
            for (int i = 0; i < 8; i++)
                #pragma unroll
                for (int j = 0; j < 8; j++)
                    acc[i][j] += af[i] * bf[j];
        }
        __syncthreads();
    }

    float* C = g_iin + (size_t)(bm * GBM) * HDIM + bn * GBN;
    #pragma unroll
    for (int i = 0; i < 8; i++) {
        float4 v0, v1;
        v0.x = acc[i][0]; v0.y = acc[i][1]; v0.z = acc[i][2]; v0.w = acc[i][3];
        v1.x = acc[i][4]; v1.y = acc[i][5]; v1.z = acc[i][6]; v1.w = acc[i][7];
        float* Crow = C + (size_t)(ty * 8 + i) * HDIM + tx * 8;
        *(float4*)(Crow)     = v0;
        *(float4*)(Crow + 4) = v1;
    }
}

// ---------------------------------------------------------------------------
// SNN kernel. CTA = (group g, slice s). W_recT rows cached as [512][64] in
// SMEM. Phase 1: recurrent loop with split own/remote gather and
// release/acquire flag exchange. Phase 2: readout + IIR for batch g*8+s.
// SMEM layout (bytes):
//   w_s     [512*64 f]   @0       131072
//   s_list  [8][512 i]   @131072   16384   (remote offset lists)
//   s_lown  [8][64 i]    @147456    2048   (own-slice offset lists)
//   s_mask  [64 u64]     @149504     512
//   s_cnt   [64 i]       @150016     256
//   s_half  [16 u32]     @150272      64
//   s_no    [8 i]        @150336      32
//   s_nr    [8 i]        @150368      32   -> total 150400
// ---------------------------------------------------------------------------
#define SNN_SMEM 150400

__global__ void __launch_bounds__(512, 1) snn_kernel(
    const float* __restrict__ b_out, float* __restrict__ out) {
    extern __shared__ char sh[];
    float*              w_s    = (float*)sh;
    int*                s_list = (int*)(sh + 131072);
    int*                s_lown = (int*)(sh + 147456);
    unsigned long long* s_mask = (unsigned long long*)(sh + 149504);
    int*                s_cnt  = (int*)(sh + 150016);
    unsigned*           s_half = (unsigned*)(sh + 150272);
    int*                s_no   = (int*)(sh + 150336);
    int*                s_nr   = (int*)(sh + 150368);

    const int g    = blockIdx.x >> 3;
    const int s    = blockIdx.x & 7;
    const int tid  = threadIdx.x;
    const int warp = tid >> 5;
    const int lane = tid & 31;
    const int b    = warp >> 1;                 // local batch 0..7
    const int d    = ((warp & 1) << 5) + lane;  // dst 0..63

    // stage W_recT slice: w_s[h][d] = g_wrecT[h][s*64+d]
    for (int idx = tid; idx < HDIM * DSTW; idx += 512)
        w_s[idx] = g_wrecT[((idx >> 6) << 9) + (s << 6) + (idx & 63)];
    if (tid < 8) { s_no[tid] = 0; s_nr[tid] = 0; }
    __syncthreads();

    const int gb = (g << 3) + b;
    float v = 0.f, ii = 0.f, aa = 0.f;
    float rec_own = 0.f;
    const float* iin = g_iin + (size_t)gb * HDIM + (s << 6) + d;
    const char*  wp  = (const char*)w_s + ((size_t)d << 2);
    const int*   lp  = s_list + (b << 9);
    const int*   lo  = s_lown + (b << 6);

    float ic = __ldg(iin);                       // t = 0 feed-forward

    for (int t = 0; t < T_STEPS; t++) {
        // ---- remote-slice gather (lists from previous step) ----
        const int nb = s_nr[b];
        float a0 = 0.f, a1 = 0.f, a2 = 0.f, a3 = 0.f;
        int j = 0;
        for (; j + 4 <= nb; j += 4) {
            int4 o = *(const int4*)(lp + j);
            a0 += *(const float*)(wp + o.x);
            a1 += *(const float*)(wp + o.y);
            a2 += *(const float*)(wp + o.z);
            a3 += *(const float*)(wp + o.w);
        }
        for (; j < nb; j++)
            a0 += *(const float*)(wp + lp[j]);
        float rec = ((a0 + a1) + (a2 + a3)) + rec_own;

        // ---- LIF-AdEx update (grouping mirrors the JAX reference) ----
        float dv   = 0.1f * ((((0.f - v) + 0.5f * expf((v - 1.f) * 2.f)) + ii) - aa);
        float vdec = v + dv;
        float idec = ii - 0.2f * ii;
        float adec = aa + 0.002f * (4.f * v - aa);
        int   z    = (vdec - 1.f) > 0.f;
        v  = z ? 0.f : vdec;
        ii = (idec + ic) + rec;
        aa = adec + (z ? 0.02f : 0.f);

        // ---- pack spike bits ----
        unsigned bal = __ballot_sync(0xffffffffu, z);
        if (lane == 0) s_half[warp] = bal;
        __syncthreads();                         // (1) gather reads done, s_half ready

        // ---- publish own masks (plain STG; ordered by the release below) ----
        if (tid < 8) {
            unsigned long long m64 =
                (unsigned long long)s_half[tid << 1] |
                ((unsigned long long)s_half[(tid << 1) + 1] << 32);
            g_zall[(((size_t)t * NG + g) * GSZ + tid) * NS + s] = m64;
        }
        __syncthreads();                         // (2) masks stored (cumulativity)
        if (tid == 0)
            st_release_gpu(&g_flag[(t * NG + g) * NS + s], 1);

        // ---- expand own masks -> own-slice lists (no remote wait needed) ----
        if (tid < 8) {
            unsigned long long m =
                (unsigned long long)s_half[tid << 1] |
                ((unsigned long long)s_half[(tid << 1) + 1] << 32);
            int cnt = 0;
            int* ol = s_lown + (tid << 6);
            const int off0 = s << 14;            // s*64 rows * 256 B
            while (m) {
                int bit = __ffsll(m) - 1;
                m &= m - 1;
                ol[cnt++] = off0 + (bit << 8);
            }
            s_no[tid] = cnt;
        }
        __syncthreads();                         // (3) own lists ready

        // prefetch next feed-forward current in the latency window
        if (t + 1 < T_STEPS)
            ic = __ldg(iin + (size_t)(t + 1) * (BATCH * HDIM));

        // ---- own-slice gather for next step (hides flag propagation) ----
        {
            const int no = s_no[b];
            float o0 = 0.f, o1 = 0.f;
            int k = 0;
            for (; k + 2 <= no; k += 2) {
                o0 += *(const float*)(wp + lo[k]);
                o1 += *(const float*)(wp + lo[k + 1]);
            }
            for (; k < no; k++)
                o0 += *(const float*)(wp + lo[k]);
            rec_own = o0 + o1;
        }

        // ---- poll peer flags + fetch masks (per-peer early fetch) ----
        if (tid < 64) {
            const int p  = tid >> 3;             // peer slice
            const int bb = tid & 7;              // batch
            const int* fp = &g_flag[(t * NG + g) * NS + p];
            while (ld_acquire_gpu(fp) == 0) {}
            unsigned long long m =
                g_zall[(((size_t)t * NG + g) * GSZ + bb) * NS + p];
            if (p == s) m = 0ull;                // own rows handled separately
            s_mask[(bb << 3) + p] = m;
            s_cnt[(bb << 3) + p]  = __popcll(m);
        }
        __syncthreads();                         // (4) masks + counts ready

        // ---- expand remote masks -> per-batch remote offset lists ----
        if (tid < 64) {
            const int bb = tid >> 3, p = tid & 7;
            int base = 0;
            #pragma unroll
            for (int q = 0; q < 7; q++)
                if (q < p) base += s_cnt[(bb << 3) + q];
            unsigned long long m = s_mask[(bb << 3) + p];
            int* out_l = s_list + (bb << 9) + base;
            const int off0 = p << 14;
            while (m) {
                int bit = __ffsll(m) - 1;
                m &= m - 1;
                *out_l++ = off0 + (bit << 8);
            }
            if (p == 7) s_nr[bb] = base + s_cnt[(bb << 3) + 7];
        }
        __syncthreads();                         // (5) remote lists ready
    }

    // ================= Phase 2: readout + IIR for batch B = g*8 + s =========
    // Visibility of peers' masks established by the per-step acquires above.
    float* y_buf = (float*)sh;                   // reuse w_s region: [500][32]
    const int B = (g << 3) + s;
    float bo = b_out[lane];
    __syncthreads();

    for (int t = warp; t < T_STEPS; t += 16) {
        const unsigned long long* mp =
            g_zall + (((size_t)t * NG + g) * GSZ + s) * NS;
        float y0 = 0.f, y1 = 0.f, y2 = 0.f, y3 = 0.f;
        #pragma unroll
        for (int w8 = 0; w8 < 8; w8++) {
            unsigned long long m = __ldcg(mp + w8);
            const float* wop = g_woutT + (w8 << 11) + lane;
            while (m) {
                int b0 = __ffsll(m) - 1; m &= m - 1;
                int b1 = -1, b2 = -1, b3 = -1;
                if (m) { b1 = __ffsll(m) - 1; m &= m - 1; }
                if (m) { b2 = __ffsll(m) - 1; m &= m - 1; }
                if (m) { b3 = __ffsll(m) - 1; m &= m - 1; }
                y0 += wop[b0 << 5];
                if (b1 >= 0) y1 += wop[b1 << 5];
                if (b2 >= 0) y2 += wop[b2 << 5];
                if (b3 >= 0) y3 += wop[b3 << 5];
            }
        }
        y_buf[t * ODIM + lane] = ((y0 + y1) + (y2 + y3)) + bo;
    }
    __syncthreads();

    if (warp == 0) {
        float o = y_buf[lane];                   // o0 = y[0]
        out[(size_t)B * ODIM + lane] = o;
        for (int t = 1; t < T_STEPS; t++) {
            float y = y_buf[t * ODIM + lane];
            o = o + 0.2231435511314f * (y - o);
            out[((size_t)t * BATCH + B) * ODIM + lane] = o;
        }
    }
}

// ---------------------------------------------------------------------------
extern "C" void kernel_launch(void* const* d_in, const int* in_sizes, int n_in,
                              void* d_out, int out_size) {
    const float* x     = (const float*)d_in[0];  // (T,B,F)
    const float* W_in  = (const float*)d_in[1];  // (H,F)
    const float* W_rec = (const float*)d_in[2];  // (H,H)
    const float* W_out = (const float*)d_in[3];  // (O,H)
    const float* b_out = (const float*)d_in[4];  // (O,)
    float* out = (float*)d_out;                  // (T,B,O)

    cudaFuncSetAttribute(snn_kernel,
                         cudaFuncAttributeMaxDynamicSharedMemorySize, SNN_SMEM);

    transpose_kernel<<<(HDIM * HDIM + 255) / 256, 256>>>(W_rec, W_out);

    dim3 ggrid(HDIM / GBN, (T_STEPS * BATCH) / GBM);  // (4, 500)
    gemm_iin_kernel<<<ggrid, 256>>>(x, W_in);

    snn_kernel<<<NG * NS, 512, SNN_SMEM>>>(b_out, out);
}